// round 16
// baseline (speedup 1.0000x reference)
#include <cuda_runtime.h>

#define Nn 50000
#define Ee 800000
#define Dd 96
#define TR 64            // rows per GEMM block
#define WT_STRIDE 98     // padded stride of transposed W (8B-aligned)

// ---------------------------------------------------------------------------
// Scratch (__device__ globals — no allocation allowed)
// ---------------------------------------------------------------------------
__device__ float4 g_p4[Nn * 24];   // P = A @ W_rel
__device__ float4 g_r4[Nn * 24];   // R = A @ W_root + b
__device__ float4 g_h4[Nn * 24];   // hidden layer h
__device__ int    g_deg[Nn];
__device__ int    g_off[Nn];       // block-local exclusive offsets
__device__ int    g_pos[Nn];
__device__ int    g_srcs[Ee];
__device__ int    g_bsum[64];

// ---------------------------------------------------------------------------
// Side stream + events for fork-join (static init; serial fallback if null)
// ---------------------------------------------------------------------------
static cudaStream_t s_side = nullptr;
static cudaEvent_t  s_fork = nullptr, s_join = nullptr;
namespace {
struct InitStreams {
    InitStreams() {
        if (cudaStreamCreateWithFlags(&s_side, cudaStreamNonBlocking) != cudaSuccess)
            s_side = nullptr;
        if (cudaEventCreateWithFlags(&s_fork, cudaEventDisableTiming) != cudaSuccess)
            s_fork = nullptr;
        if (cudaEventCreateWithFlags(&s_join, cudaEventDisableTiming) != cudaSuccess)
            s_join = nullptr;
    }
} s_init;
}

// ---------------------------------------------------------------------------
// CSR build
// ---------------------------------------------------------------------------
__global__ void k_zero_counts() {
    int i = blockIdx.x * blockDim.x + threadIdx.x;
    if (i < Nn) g_deg[i] = 0;
}

__global__ void __launch_bounds__(256)
k_hist(const int* __restrict__ ei) {
    int t = blockIdx.x * blockDim.x + threadIdx.x;
    if (t >= Ee / 4) return;
    int4 d = reinterpret_cast<const int4*>(ei + Ee)[t];
    if ((unsigned)d.x < (unsigned)Nn) atomicAdd(&g_deg[d.x], 1);
    if ((unsigned)d.y < (unsigned)Nn) atomicAdd(&g_deg[d.y], 1);
    if ((unsigned)d.z < (unsigned)Nn) atomicAdd(&g_deg[d.z], 1);
    if ((unsigned)d.w < (unsigned)Nn) atomicAdd(&g_deg[d.w], 1);
}

__global__ void k_scan1() {
    __shared__ int sm[1024];
    int i = blockIdx.x * 1024 + threadIdx.x;
    int v = (i < Nn) ? g_deg[i] : 0;
    sm[threadIdx.x] = v;
    __syncthreads();
    for (int off = 1; off < 1024; off <<= 1) {
        int t = (threadIdx.x >= off) ? sm[threadIdx.x - off] : 0;
        __syncthreads();
        sm[threadIdx.x] += t;
        __syncthreads();
    }
    if (i < Nn) { g_off[i] = sm[threadIdx.x] - v; g_pos[i] = 0; }
    if (threadIdx.x == 1023) g_bsum[blockIdx.x] = sm[1023];
}

__global__ void k_scan2() {
    __shared__ int sm[64];
    int nblk = (Nn + 1023) / 1024;
    int v = (threadIdx.x < nblk) ? g_bsum[threadIdx.x] : 0;
    sm[threadIdx.x] = v;
    __syncthreads();
    for (int off = 1; off < 64; off <<= 1) {
        int t = (threadIdx.x >= off) ? sm[threadIdx.x - off] : 0;
        __syncthreads();
        sm[threadIdx.x] += t;
        __syncthreads();
    }
    g_bsum[threadIdx.x] = sm[threadIdx.x] - v;
}

__global__ void __launch_bounds__(256)
k_fill(const int* __restrict__ ei) {
    int t = blockIdx.x * blockDim.x + threadIdx.x;
    if (t >= Ee / 4) return;
    int4 s = reinterpret_cast<const int4*>(ei)[t];
    int4 d = reinterpret_cast<const int4*>(ei + Ee)[t];
#pragma unroll
    for (int q = 0; q < 4; q++) {
        int ss = (&s.x)[q], dd = (&d.x)[q];
        if ((unsigned)ss >= (unsigned)Nn || (unsigned)dd >= (unsigned)Nn) continue;
        int slot = g_off[dd] + g_bsum[dd >> 10] + atomicAdd(&g_pos[dd], 1);
        g_srcs[slot] = ss;
    }
}

// ---------------------------------------------------------------------------
// Two-output GEMM: P = A @ W_rel ; R = A @ W_root + bias.  (unchanged)
// ---------------------------------------------------------------------------
__global__ void __launch_bounds__(192, 3)
k_gemm2(const float* __restrict__ xin,
        const float* __restrict__ Wrel,
        const float* __restrict__ Wroot,
        const float* __restrict__ bias,
        int use_h_in) {
    extern __shared__ float sm[];
    float* shWT = sm;                       // 96 * 98
    float* shA  = sm + 96 * WT_STRIDE;      // 64 * 96

    const float* A = use_h_in ? (const float*)g_h4 : xin;

    const int tx   = threadIdx.x;           // 0..23
    const int ty   = threadIdx.y;           // 0..7
    const int tid  = ty * 24 + tx;
    const int row0 = blockIdx.x * TR;

#pragma unroll
    for (int m = 0; m < 8; m++) {
        int idx = tid + 192 * m;
        int r  = idx / 24;
        int kc = idx - r * 24;
        int gr = row0 + r;
        float4 v = make_float4(0.f, 0.f, 0.f, 0.f);
        if (gr < Nn) v = reinterpret_cast<const float4*>(A + gr * Dd)[kc];
        reinterpret_cast<float4*>(shA + r * Dd)[kc] = v;
    }

    for (int pass = 0; pass < 2; pass++) {
        const float* W = pass ? Wroot : Wrel;
        __syncthreads();

#pragma unroll
        for (int m = 0; m < 12; m++) {
            int t4 = tid + 192 * m;
            float4 v = reinterpret_cast<const float4*>(W)[t4];
            int t = t4 * 4;
            int k = t / 96, c = t - k * 96;
            shWT[(c + 0) * WT_STRIDE + k] = v.x;
            shWT[(c + 1) * WT_STRIDE + k] = v.y;
            shWT[(c + 2) * WT_STRIDE + k] = v.z;
            shWT[(c + 3) * WT_STRIDE + k] = v.w;
        }
        __syncthreads();

        unsigned long long acc[8][4];
#pragma unroll
        for (int i = 0; i < 8; i++)
#pragma unroll
            for (int c = 0; c < 4; c++) acc[i][c] = 0ull;

#pragma unroll 4
        for (int kk = 0; kk < Dd; kk += 2) {
            unsigned long long w[4];
#pragma unroll
            for (int c = 0; c < 4; c++)
                w[c] = *reinterpret_cast<const unsigned long long*>(
                           &shWT[(tx + 24 * c) * WT_STRIDE + kk]);
#pragma unroll
            for (int i = 0; i < 8; i++) {
                unsigned long long a = *reinterpret_cast<const unsigned long long*>(
                                           &shA[(ty * 8 + i) * Dd + kk]);
#pragma unroll
                for (int c = 0; c < 4; c++)
                    asm("fma.rn.f32x2 %0, %1, %2, %0;"
                        : "+l"(acc[i][c]) : "l"(a), "l"(w[c]));
            }
        }

        float* O = pass ? (float*)g_r4 : (float*)g_p4;
#pragma unroll
        for (int i = 0; i < 8; i++) {
            int gr = row0 + ty * 8 + i;
            if (gr < Nn) {
#pragma unroll
                for (int c = 0; c < 4; c++) {
                    float lo = __uint_as_float((unsigned)(acc[i][c] & 0xFFFFFFFFull));
                    float hi = __uint_as_float((unsigned)(acc[i][c] >> 32));
                    float s = lo + hi;
                    if (pass) s += bias[tx + 24 * c];
                    O[gr * Dd + tx + 24 * c] = s;
                }
            }
        }
    }
}

// ---------------------------------------------------------------------------
// Fused gather v2: 4 nodes per warp, 8 lanes per node (all 32 lanes active).
// Lane sl of sub-warp handles float4 columns sl, sl+8, sl+16 of its node.
// out[n] = relu?( sum_{src in N(n)} P[src] + R[n] ).
// ---------------------------------------------------------------------------
__global__ void __launch_bounds__(256)
k_gather(float4* __restrict__ outbuf, int use_h_out, int do_relu) {
    int gwarp = (blockIdx.x * blockDim.x + threadIdx.x) >> 5;
    int sub   = (threadIdx.x >> 3) & 3;
    int sl    = threadIdx.x & 7;
    int node  = gwarp * 4 + sub;
    if (node >= Nn) return;
    float4* O = use_h_out ? (float4*)g_h4 : outbuf;

    int j   = g_off[node] + g_bsum[node >> 10];
    int end = j + g_deg[node];

    const float4* Rrow = g_r4 + node * 24;
    float4 a0 = Rrow[sl];
    float4 a1 = Rrow[sl + 8];
    float4 a2 = Rrow[sl + 16];

    for (; j + 1 < end; j += 2) {
        int s0 = g_srcs[j];        // same address across 8-lane group: broadcast
        int s1 = g_srcs[j + 1];
        const float4* r0 = g_p4 + s0 * 24;
        const float4* r1 = g_p4 + s1 * 24;
        float4 v00 = r0[sl], v01 = r0[sl + 8], v02 = r0[sl + 16];
        float4 v10 = r1[sl], v11 = r1[sl + 8], v12 = r1[sl + 16];
        a0.x += v00.x + v10.x; a0.y += v00.y + v10.y;
        a0.z += v00.z + v10.z; a0.w += v00.w + v10.w;
        a1.x += v01.x + v11.x; a1.y += v01.y + v11.y;
        a1.z += v01.z + v11.z; a1.w += v01.w + v11.w;
        a2.x += v02.x + v12.x; a2.y += v02.y + v12.y;
        a2.z += v02.z + v12.z; a2.w += v02.w + v12.w;
    }
    if (j < end) {
        const float4* r0 = g_p4 + g_srcs[j] * 24;
        float4 v0 = r0[sl], v1 = r0[sl + 8], v2 = r0[sl + 16];
        a0.x += v0.x; a0.y += v0.y; a0.z += v0.z; a0.w += v0.w;
        a1.x += v1.x; a1.y += v1.y; a1.z += v1.z; a1.w += v1.w;
        a2.x += v2.x; a2.y += v2.y; a2.z += v2.z; a2.w += v2.w;
    }
    if (do_relu) {
        a0.x = fmaxf(a0.x, 0.f); a0.y = fmaxf(a0.y, 0.f);
        a0.z = fmaxf(a0.z, 0.f); a0.w = fmaxf(a0.w, 0.f);
        a1.x = fmaxf(a1.x, 0.f); a1.y = fmaxf(a1.y, 0.f);
        a1.z = fmaxf(a1.z, 0.f); a1.w = fmaxf(a1.w, 0.f);
        a2.x = fmaxf(a2.x, 0.f); a2.y = fmaxf(a2.y, 0.f);
        a2.z = fmaxf(a2.z, 0.f); a2.w = fmaxf(a2.w, 0.f);
    }
    float4* Orow = O + node * 24;
    Orow[sl]      = a0;
    Orow[sl + 8]  = a1;
    Orow[sl + 16] = a2;
}

// ---------------------------------------------------------------------------
extern "C" void kernel_launch(void* const* d_in, const int* in_sizes, int n_in,
                              void* d_out, int out_size) {
    const float* x    = (const float*)d_in[0];
    const int*   ei   = (const int*)d_in[1];   // int32 (JAX x64 disabled)
    const float* W1r  = (const float*)d_in[2];
    const float* b1   = (const float*)d_in[3];
    const float* W1o  = (const float*)d_in[4];
    const float* W2r  = (const float*)d_in[5];
    const float* b2   = (const float*)d_in[6];
    const float* W2o  = (const float*)d_in[7];
    float4*      out4 = (float4*)d_out;

    const int smem_bytes = (96 * WT_STRIDE + TR * Dd) * (int)sizeof(float); // 62208
    cudaFuncSetAttribute(k_gemm2,
                         cudaFuncAttributeMaxDynamicSharedMemorySize, smem_bytes);

    const int node_blocks   = (Nn + 255) / 256;
    const int e4_blocks     = (Ee / 4 + 255) / 256;
    const int scan_blocks   = (Nn + 1023) / 1024;
    const int gather_blocks = ((Nn + 3) / 4 * 32 + 255) / 256;   // 4 nodes/warp
    const int gemm_blocks   = (Nn + TR - 1) / TR;

    const bool par = (s_side != nullptr) && (s_fork != nullptr) && (s_join != nullptr);

    // ---- GEMM1: P1 = x@W1r, R1 = x@W1o + b1 (no CSR dependency) ----
    if (par) {
        cudaEventRecord(s_fork, 0);
        cudaStreamWaitEvent(s_side, s_fork, 0);
        k_gemm2<<<gemm_blocks, dim3(24, 8), smem_bytes, s_side>>>(
            x, W1r, W1o, b1, /*use_h_in=*/0);
        cudaEventRecord(s_join, s_side);
    } else {
        k_gemm2<<<gemm_blocks, dim3(24, 8), smem_bytes>>>(
            x, W1r, W1o, b1, /*use_h_in=*/0);
    }

    // ---- CSR build (main stream, concurrent with GEMM1) ----
    k_zero_counts<<<node_blocks, 256>>>();
    k_hist<<<e4_blocks, 256>>>(ei);
    k_scan1<<<scan_blocks, 1024>>>();
    k_scan2<<<1, 64>>>();
    k_fill<<<e4_blocks, 256>>>(ei);

    // ---- join, then layer-1 gather: h = relu(segsum(P1) + R1) ----
    if (par) cudaStreamWaitEvent(0, s_join, 0);
    k_gather<<<gather_blocks, 256>>>(out4, /*use_h_out=*/1, /*do_relu=*/1);

    // ---- layer 2 ----
    k_gemm2<<<gemm_blocks, dim3(24, 8), smem_bytes>>>(
        x, W2r, W2o, b2, /*use_h_in=*/1);
    k_gather<<<gather_blocks, 256>>>(out4, /*use_h_out=*/0, /*do_relu=*/0);
}

// round 17
// speedup vs baseline: 1.0534x; 1.0534x over previous
#include <cuda_runtime.h>

#define Nn 50000
#define Ee 800000
#define Dd 96
#define TR 64            // rows per GEMM block
#define WT_STRIDE 98     // padded stride of transposed W (8B-aligned)
#define CAP 96           // slot capacity per node (Poisson(16) => never exceeded)
#define OVF_CAP 4096

// ---------------------------------------------------------------------------
// Scratch (__device__ globals — no allocation allowed)
// ---------------------------------------------------------------------------
__device__ float4 g_p4[Nn * 24];   // P = A @ W_rel
__device__ float4 g_r4[Nn * 24];   // R = A @ W_root + b
__device__ float4 g_h4[Nn * 24];   // hidden layer h
__device__ int    g_pos[Nn];       // per-node fill cursor == degree
__device__ int    g_slots[Nn * CAP];  // bucket CSR: src ids per dst
__device__ int    g_ovf_cnt;
__device__ int    g_ovf[2 * OVF_CAP]; // overflow (dst,src) pairs

// ---------------------------------------------------------------------------
// Side stream + events for fork-join (static init; serial fallback if null)
// ---------------------------------------------------------------------------
static cudaStream_t s_side = nullptr;
static cudaEvent_t  s_fork = nullptr, s_join = nullptr;
namespace {
struct InitStreams {
    InitStreams() {
        if (cudaStreamCreateWithFlags(&s_side, cudaStreamNonBlocking) != cudaSuccess)
            s_side = nullptr;
        if (cudaEventCreateWithFlags(&s_fork, cudaEventDisableTiming) != cudaSuccess)
            s_fork = nullptr;
        if (cudaEventCreateWithFlags(&s_join, cudaEventDisableTiming) != cudaSuccess)
            s_join = nullptr;
    }
} s_init;
}

// ---------------------------------------------------------------------------
// Bucket-CSR build: zero cursors, then direct slotted fill (no scan needed)
// ---------------------------------------------------------------------------
__global__ void k_zero_pos() {
    int i = blockIdx.x * blockDim.x + threadIdx.x;
    if (i < Nn) g_pos[i] = 0;
    if (i == 0) g_ovf_cnt = 0;
}

__global__ void __launch_bounds__(256)
k_fill(const int* __restrict__ ei) {
    int t = blockIdx.x * blockDim.x + threadIdx.x;
    if (t >= Ee / 4) return;
    int4 s = reinterpret_cast<const int4*>(ei)[t];
    int4 d = reinterpret_cast<const int4*>(ei + Ee)[t];
#pragma unroll
    for (int q = 0; q < 4; q++) {
        int ss = (&s.x)[q], dd = (&d.x)[q];
        if ((unsigned)ss >= (unsigned)Nn || (unsigned)dd >= (unsigned)Nn) continue;
        int slot = atomicAdd(&g_pos[dd], 1);
        if (slot < CAP) {
            g_slots[dd * CAP + slot] = ss;
        } else {
            int o = atomicAdd(&g_ovf_cnt, 1);
            if (o < OVF_CAP) { g_ovf[2 * o] = dd; g_ovf[2 * o + 1] = ss; }
        }
    }
}

// ---------------------------------------------------------------------------
// Two-output GEMM: P = A @ W_rel ; R = A @ W_root + bias.  (unchanged)
// ---------------------------------------------------------------------------
__global__ void __launch_bounds__(192, 3)
k_gemm2(const float* __restrict__ xin,
        const float* __restrict__ Wrel,
        const float* __restrict__ Wroot,
        const float* __restrict__ bias,
        int use_h_in) {
    extern __shared__ float sm[];
    float* shWT = sm;                       // 96 * 98
    float* shA  = sm + 96 * WT_STRIDE;      // 64 * 96

    const float* A = use_h_in ? (const float*)g_h4 : xin;

    const int tx   = threadIdx.x;           // 0..23
    const int ty   = threadIdx.y;           // 0..7
    const int tid  = ty * 24 + tx;
    const int row0 = blockIdx.x * TR;

#pragma unroll
    for (int m = 0; m < 8; m++) {
        int idx = tid + 192 * m;
        int r  = idx / 24;
        int kc = idx - r * 24;
        int gr = row0 + r;
        float4 v = make_float4(0.f, 0.f, 0.f, 0.f);
        if (gr < Nn) v = reinterpret_cast<const float4*>(A + gr * Dd)[kc];
        reinterpret_cast<float4*>(shA + r * Dd)[kc] = v;
    }

    for (int pass = 0; pass < 2; pass++) {
        const float* W = pass ? Wroot : Wrel;
        __syncthreads();

#pragma unroll
        for (int m = 0; m < 12; m++) {
            int t4 = tid + 192 * m;
            float4 v = reinterpret_cast<const float4*>(W)[t4];
            int t = t4 * 4;
            int k = t / 96, c = t - k * 96;
            shWT[(c + 0) * WT_STRIDE + k] = v.x;
            shWT[(c + 1) * WT_STRIDE + k] = v.y;
            shWT[(c + 2) * WT_STRIDE + k] = v.z;
            shWT[(c + 3) * WT_STRIDE + k] = v.w;
        }
        __syncthreads();

        unsigned long long acc[8][4];
#pragma unroll
        for (int i = 0; i < 8; i++)
#pragma unroll
            for (int c = 0; c < 4; c++) acc[i][c] = 0ull;

#pragma unroll 4
        for (int kk = 0; kk < Dd; kk += 2) {
            unsigned long long w[4];
#pragma unroll
            for (int c = 0; c < 4; c++)
                w[c] = *reinterpret_cast<const unsigned long long*>(
                           &shWT[(tx + 24 * c) * WT_STRIDE + kk]);
#pragma unroll
            for (int i = 0; i < 8; i++) {
                unsigned long long a = *reinterpret_cast<const unsigned long long*>(
                                           &shA[(ty * 8 + i) * Dd + kk]);
#pragma unroll
                for (int c = 0; c < 4; c++)
                    asm("fma.rn.f32x2 %0, %1, %2, %0;"
                        : "+l"(acc[i][c]) : "l"(a), "l"(w[c]));
            }
        }

        float* O = pass ? (float*)g_r4 : (float*)g_p4;
#pragma unroll
        for (int i = 0; i < 8; i++) {
            int gr = row0 + ty * 8 + i;
            if (gr < Nn) {
#pragma unroll
                for (int c = 0; c < 4; c++) {
                    float lo = __uint_as_float((unsigned)(acc[i][c] & 0xFFFFFFFFull));
                    float hi = __uint_as_float((unsigned)(acc[i][c] >> 32));
                    float s = lo + hi;
                    if (pass) s += bias[tx + 24 * c];
                    O[gr * Dd + tx + 24 * c] = s;
                }
            }
        }
    }
}

// ---------------------------------------------------------------------------
// Fused gather (round-13 mapping): one warp per node, 24 active float4 lanes,
// 2-edge unroll. out[n] = relu?( sum_{src in N(n)} P[src] + R[n] ).
// Overflow entries (normally none) handled inline before relu.
// ---------------------------------------------------------------------------
__global__ void __launch_bounds__(256)
k_gather(float4* __restrict__ outbuf, int use_h_out, int do_relu) {
    int node = (blockIdx.x * blockDim.x + threadIdx.x) >> 5;
    if (node >= Nn) return;
    int lane = threadIdx.x & 31;
    if (lane >= 24) return;
    float4* O = use_h_out ? (float4*)g_h4 : outbuf;

    const int* idx = g_slots + node * CAP;
    int deg = g_pos[node];
    int end = deg < CAP ? deg : CAP;

    float4 r = g_r4[node * 24 + lane];
    float ax = r.x, ay = r.y, az = r.z, aw = r.w;
    int j = 0;
    for (; j + 1 < end; j += 2) {
        int s0 = idx[j], s1 = idx[j + 1];   // broadcast within warp
        float4 v0 = g_p4[s0 * 24 + lane];
        float4 v1 = g_p4[s1 * 24 + lane];
        ax += v0.x + v1.x; ay += v0.y + v1.y;
        az += v0.z + v1.z; aw += v0.w + v1.w;
    }
    if (j < end) {
        float4 v = g_p4[idx[j] * 24 + lane];
        ax += v.x; ay += v.y; az += v.z; aw += v.w;
    }
    // overflow list (empty in practice; counter load is a broadcast L2 hit)
    int ovf = g_ovf_cnt;
    if (ovf > 0) {
        if (ovf > OVF_CAP) ovf = OVF_CAP;
        for (int o = 0; o < ovf; o++) {
            if (g_ovf[2 * o] == node) {
                float4 v = g_p4[g_ovf[2 * o + 1] * 24 + lane];
                ax += v.x; ay += v.y; az += v.z; aw += v.w;
            }
        }
    }
    if (do_relu) {
        ax = fmaxf(ax, 0.f); ay = fmaxf(ay, 0.f);
        az = fmaxf(az, 0.f); aw = fmaxf(aw, 0.f);
    }
    O[node * 24 + lane] = make_float4(ax, ay, az, aw);
}

// ---------------------------------------------------------------------------
extern "C" void kernel_launch(void* const* d_in, const int* in_sizes, int n_in,
                              void* d_out, int out_size) {
    const float* x    = (const float*)d_in[0];
    const int*   ei   = (const int*)d_in[1];   // int32 (JAX x64 disabled)
    const float* W1r  = (const float*)d_in[2];
    const float* b1   = (const float*)d_in[3];
    const float* W1o  = (const float*)d_in[4];
    const float* W2r  = (const float*)d_in[5];
    const float* b2   = (const float*)d_in[6];
    const float* W2o  = (const float*)d_in[7];
    float4*      out4 = (float4*)d_out;

    const int smem_bytes = (96 * WT_STRIDE + TR * Dd) * (int)sizeof(float); // 62208
    cudaFuncSetAttribute(k_gemm2,
                         cudaFuncAttributeMaxDynamicSharedMemorySize, smem_bytes);

    const int node_blocks   = (Nn + 255) / 256;
    const int e4_blocks     = (Ee / 4 + 255) / 256;
    const int gather_blocks = (Nn * 32 + 255) / 256;
    const int gemm_blocks   = (Nn + TR - 1) / TR;

    const bool par = (s_side != nullptr) && (s_fork != nullptr) && (s_join != nullptr);

    // ---- GEMM1: P1 = x@W1r, R1 = x@W1o + b1 (no CSR dependency) ----
    if (par) {
        cudaEventRecord(s_fork, 0);
        cudaStreamWaitEvent(s_side, s_fork, 0);
        k_gemm2<<<gemm_blocks, dim3(24, 8), smem_bytes, s_side>>>(
            x, W1r, W1o, b1, /*use_h_in=*/0);
        cudaEventRecord(s_join, s_side);
    } else {
        k_gemm2<<<gemm_blocks, dim3(24, 8), smem_bytes>>>(
            x, W1r, W1o, b1, /*use_h_in=*/0);
    }

    // ---- bucket-CSR build (main stream, concurrent with GEMM1) ----
    k_zero_pos<<<node_blocks, 256>>>();
    k_fill<<<e4_blocks, 256>>>(ei);

    // ---- join, then layer-1 gather: h = relu(segsum(P1) + R1) ----
    if (par) cudaStreamWaitEvent(0, s_join, 0);
    k_gather<<<gather_blocks, 256>>>(out4, /*use_h_out=*/1, /*do_relu=*/1);

    // ---- layer 2 ----
    k_gemm2<<<gemm_blocks, dim3(24, 8), smem_bytes>>>(
        x, W2r, W2o, b2, /*use_h_in=*/1);
    k_gather<<<gather_blocks, 256>>>(out4, /*use_h_out=*/0, /*do_relu=*/0);
}